// round 1
// baseline (speedup 1.0000x reference)
#include <cuda_runtime.h>
#include <cstdint>

// ---------------- packed f32x2 helpers (sm_100+) ----------------
__device__ __forceinline__ unsigned long long packf2(float lo, float hi) {
    unsigned long long r;
    asm("mov.b64 %0, {%1, %2};" : "=l"(r)
        : "r"(__float_as_uint(lo)), "r"(__float_as_uint(hi)));
    return r;
}
__device__ __forceinline__ void unpackf2(unsigned long long p, float& lo, float& hi) {
    unsigned int a, b;
    asm("mov.b64 {%0, %1}, %2;" : "=r"(a), "=r"(b) : "l"(p));
    lo = __uint_as_float(a);
    hi = __uint_as_float(b);
}
__device__ __forceinline__ unsigned long long fmaf2(unsigned long long a,
                                                    unsigned long long b,
                                                    unsigned long long c) {
    unsigned long long d;
    asm("fma.rn.f32x2 %0, %1, %2, %3;" : "=l"(d) : "l"(a), "l"(b), "l"(c));
    return d;
}

// ---------------- scratch (device globals; no allocation) ----------------
#define NIMG 800
__device__ float g_h1[NIMG * 4 * 30 * 30];   // conv1 -> relu -> pool output
__device__ float g_stats1[NIMG * 8];         // per-image [oc][sum,sumsq]
__device__ float g_w2f[8 * 4 * 81];          // conv2 weights with bn1 folded
__device__ float g_b2f[8];
__device__ float g_h2[NIMG * 8 * 5 * 5];     // conv2 -> relu -> pool output
__device__ float g_stats2[NIMG * 16];        // per-image [oc][sum,sumsq]
__device__ float g_fc1wf[16 * 200];          // fc1 weights with bn2 folded
__device__ float g_fc1bf[16];
__device__ float g_zR[NIMG * 5];             // per frame: z0 z1 r00 r01 r11

// =================================================================
// Kernel 1: conv1 (3->4, 9x9, stride2) + bias + relu + maxpool2 + stats
// grid = 800 images, block = 192 threads.
// thread (tid<180): py = tid/6 (pooled row), pxg = tid%6 (5 pooled cols).
// Two passes over the two conv rows of the pool window; 10 conv cols held as
// 5 f32x2 accumulator pairs per output channel.
// =================================================================
__global__ __launch_bounds__(192) void k_conv1(const float* __restrict__ x,
                                               const float* __restrict__ w1,
                                               const float* __restrict__ b1) {
    __shared__ float2 sw[972];    // duplicated weight pairs {w,w}
    __shared__ float sred[6 * 8];
    const int n = blockIdx.x;
    const int tid = threadIdx.x;

    for (int i = tid; i < 972; i += 192) {
        float w = w1[i];
        sw[i] = make_float2(w, w);
    }
    __syncthreads();

    float psum[4] = {0.f, 0.f, 0.f, 0.f};
    float psq[4] = {0.f, 0.f, 0.f, 0.f};

    if (tid < 180) {
        const int py = tid / 6;
        const int pxg = tid % 6;
        const float* xb = x + (long)n * 49152;   // 128*128*3
        const float bb0 = b1[0], bb1 = b1[1], bb2 = b1[2], bb3 = b1[3];
        const float bbs[4] = {bb0, bb1, bb2, bb3};

        float fin[5][4];

        #pragma unroll
        for (int dy = 0; dy < 2; ++dy) {
            unsigned long long acc[5][4];
            #pragma unroll
            for (int u = 0; u < 5; ++u)
                #pragma unroll
                for (int oc = 0; oc < 4; ++oc) acc[u][oc] = 0ull;

            for (int c = 0; c < 3; ++c) {
                for (int ky = 0; ky < 9; ++ky) {
                    const int ir = 4 * py + 2 * dy + ky;
                    const float* row = xb + ((long)ir * 128 + pxg * 20) * 3 + c;
                    float v[27];
                    #pragma unroll
                    for (int j = 0; j < 27; ++j) v[j] = row[3 * j];

                    const float2* wbase = &sw[(c * 9 + ky) * 9];
                    #pragma unroll
                    for (int kx = 0; kx < 9; ++kx) {
                        unsigned long long pv[5];
                        #pragma unroll
                        for (int u = 0; u < 5; ++u)
                            pv[u] = packf2(v[4 * u + kx], v[4 * u + kx + 2]);
                        #pragma unroll
                        for (int oc = 0; oc < 4; ++oc) {
                            unsigned long long wp =
                                *reinterpret_cast<const unsigned long long*>(
                                    &wbase[oc * 243 + kx]);
                            #pragma unroll
                            for (int u = 0; u < 5; ++u)
                                acc[u][oc] = fmaf2(pv[u], wp, acc[u][oc]);
                        }
                    }
                }
            }
            #pragma unroll
            for (int u = 0; u < 5; ++u) {
                #pragma unroll
                for (int oc = 0; oc < 4; ++oc) {
                    float lo, hi;
                    unpackf2(acc[u][oc], lo, hi);
                    float b = bbs[oc];
                    float m = fmaxf(fmaxf(lo + b, 0.f), fmaxf(hi + b, 0.f));
                    if (dy == 0) fin[u][oc] = m;
                    else         fin[u][oc] = fmaxf(fin[u][oc], m);
                }
            }
        }
        #pragma unroll
        for (int oc = 0; oc < 4; ++oc) {
            #pragma unroll
            for (int u = 0; u < 5; ++u) {
                float vv = fin[u][oc];
                g_h1[(((long)n * 4 + oc) * 30 + py) * 30 + pxg * 5 + u] = vv;
                psum[oc] += vv;
                psq[oc] += vv * vv;
            }
        }
    }

    // deterministic block reduction of 8 partials
    const int lane = tid & 31, wid = tid >> 5;
    #pragma unroll
    for (int oc = 0; oc < 4; ++oc) {
        #pragma unroll
        for (int off = 16; off > 0; off >>= 1) {
            psum[oc] += __shfl_down_sync(0xffffffffu, psum[oc], off);
            psq[oc]  += __shfl_down_sync(0xffffffffu, psq[oc],  off);
        }
    }
    if (lane == 0) {
        #pragma unroll
        for (int oc = 0; oc < 4; ++oc) {
            sred[wid * 8 + oc * 2 + 0] = psum[oc];
            sred[wid * 8 + oc * 2 + 1] = psq[oc];
        }
    }
    __syncthreads();
    if (tid < 8) {
        float s = 0.f;
        #pragma unroll
        for (int w = 0; w < 6; ++w) s += sred[w * 8 + tid];
        g_stats1[n * 8 + tid] = s;
    }
}

// =================================================================
// Kernel 2: bn1 statistics finalize + fold bn1 into conv2 weights/bias
// =================================================================
__global__ void k_bn1fold(const float* __restrict__ bn1g,
                          const float* __restrict__ bn1b,
                          const float* __restrict__ w2,
                          const float* __restrict__ b2) {
    __shared__ float tot[8];
    __shared__ float scale[4], shift[4];
    const int tid = threadIdx.x, lane = tid & 31, wid = tid >> 5;

    if (wid < 8) {
        float s = 0.f;
        for (int nn = lane; nn < NIMG; nn += 32) s += g_stats1[nn * 8 + wid];
        #pragma unroll
        for (int off = 16; off > 0; off >>= 1)
            s += __shfl_down_sync(0xffffffffu, s, off);
        if (lane == 0) tot[wid] = s;
    }
    __syncthreads();
    if (tid < 4) {
        const float cnt = 800.f * 30.f * 30.f;
        float mean = tot[tid * 2] / cnt;
        float var = tot[tid * 2 + 1] / cnt - mean * mean;
        float sc = bn1g[tid] * rsqrtf(var + 1e-5f);
        scale[tid] = sc;
        shift[tid] = bn1b[tid] - mean * sc;
    }
    __syncthreads();
    for (int i = tid; i < 2592; i += 256) {
        int ic = (i / 81) & 3;
        g_w2f[i] = w2[i] * scale[ic];
    }
    if (wid < 8) {
        float s = 0.f;
        for (int k = lane; k < 324; k += 32) {
            int ic = k / 81;
            s += w2[wid * 324 + k] * shift[ic];
        }
        #pragma unroll
        for (int off = 16; off > 0; off >>= 1)
            s += __shfl_down_sync(0xffffffffu, s, off);
        if (lane == 0) g_b2f[wid] = b2[wid] + s;
    }
}

// =================================================================
// Kernel 3: conv2 (4->8, 9x9, s2) on bn1-folded weights + relu + pool + stats
// block = one image; 80 workers = 10 conv rows x 2 oc-halves x 4 input ch.
// Partial sums over input channels combined in smem, then pooled.
// =================================================================
__global__ __launch_bounds__(128) void k_conv2() {
    __shared__ float sh1[3600];
    __shared__ float swt[2592];
    __shared__ float sb[8];
    __shared__ float part[3200];   // [cr(10)][oh(2)][c(4)][col(10)][o(4)]
    __shared__ float pooled[200];
    const int n = blockIdx.x;
    const int tid = threadIdx.x;

    for (int i = tid; i < 3600; i += 128) sh1[i] = g_h1[(long)n * 3600 + i];
    for (int i = tid; i < 2592; i += 128) swt[i] = g_w2f[i];
    if (tid < 8) sb[tid] = g_b2f[tid];
    __syncthreads();

    if (tid < 80) {
        const int cr = tid / 8;
        const int oh = (tid % 8) / 4;
        const int c = tid % 4;
        unsigned long long acc[5][4];
        #pragma unroll
        for (int u = 0; u < 5; ++u)
            #pragma unroll
            for (int o = 0; o < 4; ++o) acc[u][o] = 0ull;

        for (int ky = 0; ky < 9; ++ky) {
            const int row = 2 * cr + ky;
            const float* vrow = &sh1[(c * 30 + row) * 30];
            float v[27];
            #pragma unroll
            for (int j = 0; j < 27; ++j) v[j] = vrow[j];
            #pragma unroll
            for (int kx = 0; kx < 9; ++kx) {
                unsigned long long pv[5];
                #pragma unroll
                for (int u = 0; u < 5; ++u)
                    pv[u] = packf2(v[4 * u + kx], v[4 * u + kx + 2]);
                #pragma unroll
                for (int o = 0; o < 4; ++o) {
                    float w = swt[((oh * 4 + o) * 4 + c) * 81 + ky * 9 + kx];
                    unsigned long long wp = packf2(w, w);
                    #pragma unroll
                    for (int u = 0; u < 5; ++u)
                        acc[u][o] = fmaf2(pv[u], wp, acc[u][o]);
                }
            }
        }
        const int base = ((cr * 2 + oh) * 4 + c) * 40;
        #pragma unroll
        for (int u = 0; u < 5; ++u)
            #pragma unroll
            for (int o = 0; o < 4; ++o) {
                float lo, hi;
                unpackf2(acc[u][o], lo, hi);
                part[base + (2 * u) * 4 + o] = lo;
                part[base + (2 * u + 1) * 4 + o] = hi;
            }
    }
    __syncthreads();

    for (int j = tid; j < 200; j += 128) {
        const int oc = j / 25, p = j % 25, py = p / 5, px = p % 5;
        const int oh = oc / 4, o = oc % 4;
        float m = 0.f;   // relu makes every candidate >= 0
        #pragma unroll
        for (int dy = 0; dy < 2; ++dy)
            #pragma unroll
            for (int dx = 0; dx < 2; ++dx) {
                int ccr = 2 * py + dy, col = 2 * px + dx;
                float s = sb[oc];
                #pragma unroll
                for (int c = 0; c < 4; ++c)
                    s += part[((ccr * 2 + oh) * 4 + c) * 40 + col * 4 + o];
                m = fmaxf(m, s);
            }
        g_h2[(long)n * 200 + j] = m;
        pooled[j] = m;
    }
    __syncthreads();
    if (tid < 16) {
        const int oc = tid / 2, s = tid % 2;
        float acc = 0.f;
        for (int p = 0; p < 25; ++p) {
            float v = pooled[oc * 25 + p];
            acc += s ? v * v : v;
        }
        g_stats2[n * 16 + tid] = acc;
    }
}

// =================================================================
// Kernel 4: bn2 finalize + fold into fc1
// =================================================================
__global__ void k_bn2fold(const float* __restrict__ bn2g,
                          const float* __restrict__ bn2b,
                          const float* __restrict__ fc1w,
                          const float* __restrict__ fc1b) {
    __shared__ float tot[16];
    __shared__ float scale[8], shift[8];
    const int tid = threadIdx.x, lane = tid & 31, wid = tid >> 5;

    if (wid < 16) {
        float s = 0.f;
        for (int nn = lane; nn < NIMG; nn += 32) s += g_stats2[nn * 16 + wid];
        #pragma unroll
        for (int off = 16; off > 0; off >>= 1)
            s += __shfl_down_sync(0xffffffffu, s, off);
        if (lane == 0) tot[wid] = s;
    }
    __syncthreads();
    if (tid < 8) {
        const float cnt = 800.f * 25.f;
        float mean = tot[tid * 2] / cnt;
        float var = tot[tid * 2 + 1] / cnt - mean * mean;
        float sc = bn2g[tid] * rsqrtf(var + 1e-5f);
        scale[tid] = sc;
        shift[tid] = bn2b[tid] - mean * sc;
    }
    __syncthreads();
    for (int i = tid; i < 3200; i += 512) {
        int k = i % 200;
        g_fc1wf[i] = fc1w[i] * scale[k / 25];
    }
    if (wid < 16) {
        float s = 0.f;
        for (int k = lane; k < 200; k += 32)
            s += fc1w[wid * 200 + k] * shift[k / 25];
        #pragma unroll
        for (int off = 16; off > 0; off >>= 1)
            s += __shfl_down_sync(0xffffffffu, s, off);
        if (lane == 0) g_fc1bf[wid] = fc1b[wid] + s;
    }
}

// =================================================================
// Kernel 5: FC stack (bn2 folded in fc1) -> z, R entries. thread per frame.
// =================================================================
__global__ __launch_bounds__(128) void k_fc(const float* __restrict__ fc2w,
                                            const float* __restrict__ fc2b,
                                            const float* __restrict__ fzw,
                                            const float* __restrict__ fzb,
                                            const float* __restrict__ fLw,
                                            const float* __restrict__ fLb) {
    __shared__ float s1w[3200], s1b[16], s2w[512], s2b[32];
    __shared__ float szw[64], szb[2], sLw[96], sLb[3];
    const int tid = threadIdx.x;
    for (int i = tid; i < 3200; i += 128) s1w[i] = g_fc1wf[i];
    for (int i = tid; i < 512; i += 128) s2w[i] = fc2w[i];
    for (int i = tid; i < 96; i += 128) sLw[i] = fLw[i];
    if (tid < 64) szw[tid] = fzw[tid];
    if (tid < 16) s1b[tid] = g_fc1bf[tid];
    if (tid < 32) s2b[tid] = fc2b[tid];
    if (tid < 2) szb[tid] = fzb[tid];
    if (tid < 3) sLb[tid] = fLb[tid];
    __syncthreads();

    const int n = blockIdx.x * 128 + tid;
    if (n < NIMG) {
        const float* f = &g_h2[(long)n * 200];
        float a1[16];
        #pragma unroll
        for (int j = 0; j < 16; ++j) a1[j] = s1b[j];
        for (int k = 0; k < 200; ++k) {
            float fv = f[k];
            #pragma unroll
            for (int j = 0; j < 16; ++j) a1[j] += s1w[j * 200 + k] * fv;
        }
        #pragma unroll
        for (int j = 0; j < 16; ++j) a1[j] = fmaxf(a1[j], 0.f);

        float z0 = szb[0], z1 = szb[1];
        float L0 = sLb[0], L1 = sLb[1], L2 = sLb[2];
        #pragma unroll
        for (int j = 0; j < 32; ++j) {
            float a = s2b[j];
            #pragma unroll
            for (int k = 0; k < 16; ++k) a += s2w[j * 16 + k] * a1[k];
            a = fmaxf(a, 0.f);
            z0 += szw[j] * a;
            z1 += szw[32 + j] * a;
            L0 += sLw[j] * a;
            L1 += sLw[32 + j] * a;
            L2 += sLw[64 + j] * a;
        }
        float* o = &g_zR[(long)n * 5];
        o[0] = z0;
        o[1] = z1;
        o[2] = L0 * L0;
        o[3] = L0 * L1;
        o[4] = L1 * L1 + L2 * L2;
    }
}

// =================================================================
// Kernel 6: Kalman filter. One warp: 8 sequences x 4 lanes (lane = state row).
// =================================================================
__global__ void k_kf(const float* __restrict__ Ag, const float* __restrict__ Bg,
                     const float* __restrict__ Cg, const float* __restrict__ Qg,
                     float* __restrict__ out) {
    const int lane = threadIdx.x;
    const int seq = lane >> 2;
    const int i = lane & 3;
    const unsigned FM = 0xffffffffu;

    float A[16], C[8];
    #pragma unroll
    for (int t = 0; t < 16; ++t) A[t] = Ag[t];
    #pragma unroll
    for (int t = 0; t < 8; ++t) C[t] = Cg[t];

    // BQB^T row i
    float BQ0 = Bg[i * 2 + 0] * Qg[0] + Bg[i * 2 + 1] * Qg[2];
    float BQ1 = Bg[i * 2 + 0] * Qg[1] + Bg[i * 2 + 1] * Qg[3];
    float bq[4];
    #pragma unroll
    for (int j = 0; j < 4; ++j)
        bq[j] = BQ0 * Bg[j * 2 + 0] + BQ1 * Bg[j * 2 + 1];

    const float* zr0 = &g_zR[(long)seq * 100 * 5];
    float h = (i == 0) ? zr0[0] : (i == 1) ? zr0[1] : 0.f;
    float s[4];
    if (i == 0)      { s[0] = zr0[2]; s[1] = zr0[3]; s[2] = 0.f; s[3] = 0.f; }
    else if (i == 1) { s[0] = zr0[3]; s[1] = zr0[4]; s[2] = 0.f; s[3] = 0.f; }
    else             { s[0] = 0.f; s[1] = 0.f; s[2] = (i == 2) ? 1.f : 0.f;
                       s[3] = (i == 3) ? 1.f : 0.f; }
    out[((long)seq * 100) * 4 + i] = h;

    for (int t = 1; t < 100; ++t) {
        const float* zp = &g_zR[((long)seq * 100 + t) * 5];
        const float zt0 = zp[0], zt1 = zp[1];
        const float R00 = zp[2], R01 = zp[3], R11 = zp[4];

        // hp = A h
        float hp = 0.f;
        #pragma unroll
        for (int j = 0; j < 4; ++j)
            hp += A[i * 4 + j] * __shfl_sync(FM, h, j, 4);

        // M = A s  (row i)
        float M[4] = {0.f, 0.f, 0.f, 0.f};
        #pragma unroll
        for (int j = 0; j < 4; ++j) {
            float aij = A[i * 4 + j];
            #pragma unroll
            for (int k = 0; k < 4; ++k)
                M[k] += aij * __shfl_sync(FM, s[k], j, 4);
        }
        // sp = M A^T + BQB^T
        float sp[4];
        #pragma unroll
        for (int k = 0; k < 4; ++k) {
            float acc = bq[k];
            #pragma unroll
            for (int j = 0; j < 4; ++j) acc += M[j] * A[k * 4 + j];
            sp[k] = acc;
        }
        // SpC^T row i
        float sct0 = sp[0] * C[0] + sp[1] * C[1] + sp[2] * C[2] + sp[3] * C[3];
        float sct1 = sp[0] * C[4] + sp[1] * C[5] + sp[2] * C[6] + sp[3] * C[7];
        // S = C SpC^T + R
        float S00 = R00, S01 = R01, S10 = R01, S11 = R11;
        #pragma unroll
        for (int j = 0; j < 4; ++j) {
            float t0 = __shfl_sync(FM, sct0, j, 4);
            float t1 = __shfl_sync(FM, sct1, j, 4);
            S00 += C[j] * t0;
            S01 += C[j] * t1;
            S10 += C[4 + j] * t0;
            S11 += C[4 + j] * t1;
        }
        float inv = 1.f / (S00 * S11 - S01 * S10);
        float i00 = S11 * inv, i01 = -S01 * inv;
        float i10 = -S10 * inv, i11 = S00 * inv;
        float K0 = sct0 * i00 + sct1 * i10;
        float K1 = sct0 * i01 + sct1 * i11;
        // alpha
        float c0h = 0.f, c1h = 0.f;
        #pragma unroll
        for (int j = 0; j < 4; ++j) {
            float hj = __shfl_sync(FM, hp, j, 4);
            c0h += C[j] * hj;
            c1h += C[4 + j] * hj;
        }
        float a0 = zt0 - c0h, a1 = zt1 - c1h;
        float hn = hp + K0 * a0 + K1 * a1;
        // (I - K C) row i
        float ikc[4];
        #pragma unroll
        for (int j = 0; j < 4; ++j)
            ikc[j] = ((i == j) ? 1.f : 0.f) - (K0 * C[j] + K1 * C[4 + j]);
        float sn[4] = {0.f, 0.f, 0.f, 0.f};
        #pragma unroll
        for (int j = 0; j < 4; ++j) {
            float wj = ikc[j];
            #pragma unroll
            for (int k = 0; k < 4; ++k)
                sn[k] += wj * __shfl_sync(FM, sp[k], j, 4);
        }
        h = hn;
        #pragma unroll
        for (int k = 0; k < 4; ++k) s[k] = sn[k];
        out[((long)seq * 100 + t) * 4 + i] = hn;
    }
}

// =================================================================
extern "C" void kernel_launch(void* const* d_in, const int* in_sizes, int n_in,
                              void* d_out, int out_size) {
    const float* x     = (const float*)d_in[0];
    const float* w1    = (const float*)d_in[1];
    const float* b1    = (const float*)d_in[2];
    const float* bn1g  = (const float*)d_in[3];
    const float* bn1b  = (const float*)d_in[4];
    const float* w2    = (const float*)d_in[5];
    const float* b2    = (const float*)d_in[6];
    const float* bn2g  = (const float*)d_in[7];
    const float* bn2b  = (const float*)d_in[8];
    const float* fc1w  = (const float*)d_in[9];
    const float* fc1b  = (const float*)d_in[10];
    const float* fc2w  = (const float*)d_in[11];
    const float* fc2b  = (const float*)d_in[12];
    const float* fzw   = (const float*)d_in[13];
    const float* fzb   = (const float*)d_in[14];
    const float* fLw   = (const float*)d_in[15];
    const float* fLb   = (const float*)d_in[16];
    const float* Amat  = (const float*)d_in[17];
    const float* Bmat  = (const float*)d_in[18];
    const float* Cmat  = (const float*)d_in[19];
    const float* Qmat  = (const float*)d_in[20];
    float* out = (float*)d_out;

    k_conv1<<<NIMG, 192>>>(x, w1, b1);
    k_bn1fold<<<1, 256>>>(bn1g, bn1b, w2, b2);
    k_conv2<<<NIMG, 128>>>();
    k_bn2fold<<<1, 512>>>(bn2g, bn2b, fc1w, fc1b);
    k_fc<<<(NIMG + 127) / 128, 128>>>(fc2w, fc2b, fzw, fzb, fLw, fLb);
    k_kf<<<1, 32>>>(Amat, Bmat, Cmat, Qmat, out);
}